// round 13
// baseline (speedup 1.0000x reference)
#include <cuda_runtime.h>
#include <cstdint>

#define T_STEPS 65536
#define HID     128
#define INS     96
#define LINW    32
#define G3      384   // 3 * HID

// Scratch (allocation-free rule: __device__ globals)
__device__ float g_igates[(size_t)(T_STEPS + 2) * G3];  // +2 rows for 2-step prefetch
__device__ float g_hbuf[(size_t)T_STEPS * LINW];

typedef unsigned long long ull;

// ---- packed f32x2 helpers (Blackwell sm_103a) ----
__device__ __forceinline__ ull pack2(float lo, float hi) {
    ull r; asm("mov.b64 %0,{%1,%2};" : "=l"(r) : "f"(lo), "f"(hi)); return r;
}
__device__ __forceinline__ void unpack2(ull p, float& lo, float& hi) {
    asm("mov.b64 {%0,%1},%2;" : "=f"(lo), "=f"(hi) : "l"(p));
}
__device__ __forceinline__ ull ffma2(ull a, ull b, ull c) {
    ull d; asm("fma.rn.f32x2 %0,%1,%2,%3;" : "=l"(d) : "l"(a), "l"(b), "l"(c)); return d;
}
__device__ __forceinline__ ull fadd2(ull a, ull b) {
    ull d; asm("add.rn.f32x2 %0,%1,%2;" : "=l"(d) : "l"(a), "l"(b)); return d;
}

// ---- fast, overflow-safe activations (err ~1e-6, well under 1e-3 budget) ----
__device__ __forceinline__ float fsigmoid(float x) {
    float e = __expf(-x);
    return __fdividef(1.0f, 1.0f + e);
}
__device__ __forceinline__ float ftanh_f(float x) {
    float ax = fabsf(x);
    float e  = __expf(-2.0f * ax);
    float t  = __fdividef(1.0f - e, 1.0f + e);
    return copysignf(t, x);
}

// ============================================================================
// Kernel A: igates[t][j] = b_ih[j] + sum_k input_GRU[t][k] * w_ih[j][k]
// ============================================================================
__global__ __launch_bounds__(384, 1) void igates_kernel(
    const float* __restrict__ in_gru,
    const float* __restrict__ w_ih,
    const float* __restrict__ b_ih)
{
    __shared__ __align__(16) float s_in[64 * INS];
    const int tid = threadIdx.x;
    const int t0  = blockIdx.x * 64;

    {
        const float4* gsrc = (const float4*)(in_gru + (size_t)t0 * INS);
        float4* sdst = (float4*)s_in;
        for (int q = tid; q < (64 * INS) / 4; q += 384) sdst[q] = gsrc[q];
    }

    ull wq[48];
    {
        const float4* wr = (const float4*)(w_ih + (size_t)tid * INS);
        #pragma unroll
        for (int q = 0; q < 24; q++) {
            float4 v = wr[q];
            wq[2 * q]     = pack2(v.x, v.y);
            wq[2 * q + 1] = pack2(v.z, v.w);
        }
    }
    const float bias = b_ih[tid];
    __syncthreads();

    for (int tt = 0; tt < 64; tt++) {
        const ulonglong2* hp2 = (const ulonglong2*)(s_in + tt * INS);
        ull a0 = 0ull, a1 = 0ull, a2 = 0ull, a3 = 0ull;
        #pragma unroll
        for (int q = 0; q < 24; q++) {
            ulonglong2 hv = hp2[q];
            if (q & 1) { a2 = ffma2(wq[2 * q], hv.x, a2); a3 = ffma2(wq[2 * q + 1], hv.y, a3); }
            else       { a0 = ffma2(wq[2 * q], hv.x, a0); a1 = ffma2(wq[2 * q + 1], hv.y, a1); }
        }
        ull s = fadd2(fadd2(a0, a2), fadd2(a1, a3));
        float lo, hi; unpack2(s, lo, hi);
        g_igates[(size_t)(t0 + tt) * G3 + tid] = lo + hi + bias;
    }
}

// ============================================================================
// Kernel B: sequential scan. ONE CTA, 256 threads, single SM.
//
// Thread (j = tid>>1, half = tid&1) owns gate rows {j, 128+j, 256+j} of w_hh
// over columns [half*64, half*64+64).
//
// Per step:
//   - prefetch igates(t+2) via __ldcs  (TWO steps of slack -> DRAM latency
//     can never land on the critical path)
//   - pass 1: r/z chains (64 FFMA2) -> reduce -> shfl -> sigmoids
//             (sigmoid MUFU chains drain under pass 2's FMA issue)
//   - pass 2: n chain (32 FFMA2, h re-read via broadcast LDS)
//   - tail:   n-reduce + shfl (c=fmaf(r,b_n,in) computes in its shadow)
//             + tanh + hnew + STS + one __syncthreads
// h double-buffered in SMEM (+16B pad: even/odd lane broadcast groups hit
// disjoint banks -> 1 wavefront per LDS.128).
// ============================================================================
__global__ __launch_bounds__(256, 1) void scan_kernel(
    const float* __restrict__ init_h,
    const float* __restrict__ w_hh,
    const float* __restrict__ b_n)
{
    // h layout per buffer: cols 0..63 at floats [0,64); cols 64..127 at [68,132)
    __shared__ __align__(16) float h_sm[2][136];

    const int tid  = threadIdx.x;
    const int j    = tid >> 1;      // hidden unit 0..127
    const int half = tid & 1;       // column half
    const uint32_t hoff = half ? 272u : 0u;

    // weights: rows {j, 128+j, 256+j}, this thread's 64 columns each
    ull wr_[32], wz_[32], wn_[32];
    {
        const float4* p;
        p = (const float4*)(w_hh + (size_t)(0 * HID + j) * HID + half * 64);
        #pragma unroll
        for (int q = 0; q < 16; q++) { float4 v = p[q]; wr_[2*q] = pack2(v.x,v.y); wr_[2*q+1] = pack2(v.z,v.w); }
        p = (const float4*)(w_hh + (size_t)(1 * HID + j) * HID + half * 64);
        #pragma unroll
        for (int q = 0; q < 16; q++) { float4 v = p[q]; wz_[2*q] = pack2(v.x,v.y); wz_[2*q+1] = pack2(v.z,v.w); }
        p = (const float4*)(w_hh + (size_t)(2 * HID + j) * HID + half * 64);
        #pragma unroll
        for (int q = 0; q < 16; q++) { float4 v = p[q]; wn_[2*q] = pack2(v.x,v.y); wn_[2*q+1] = pack2(v.z,v.w); }
    }

    // init h buffer 0 (padded layout)
    if (tid < HID) {
        int idx = tid + ((tid >> 6) << 2);
        h_sm[0][idx] = init_h[tid];
    }

    const int  jidx = j + ((j >> 6) << 2);
    const float bni = b_n[j];
    float h_old = init_h[j];
    // igates for step 0 (current) and step 1 (next), loaded up front
    float ir  = __ldcs(&g_igates[j]);
    float iz  = __ldcs(&g_igates[HID + j]);
    float inq = __ldcs(&g_igates[2 * HID + j]);
    float ir1 = __ldcs(&g_igates[G3 + j]);
    float iz1 = __ldcs(&g_igates[G3 + HID + j]);
    float in1 = __ldcs(&g_igates[G3 + 2 * HID + j]);
    __syncthreads();

    for (int t = 0; t < T_STEPS; t++) {
        // ---- prefetch igates for step t+2 (TWO steps of DRAM slack) ----
        const float* nx = g_igates + (size_t)(t + 2) * G3 + j;
        float ir2 = __ldcs(nx);
        float iz2 = __ldcs(nx + HID);
        float in2 = __ldcs(nx + 2 * HID);

        const ulonglong2* hp =
            (const ulonglong2*)((const char*)&h_sm[t & 1][0] + hoff);

        // ---- pass 1: r and z gate chains ----
        float r, z;
        {
            ull a0 = 0ull, a1 = 0ull, a2 = 0ull, a3 = 0ull;
            #pragma unroll
            for (int q = 0; q < 16; q++) {
                ulonglong2 hv = hp[q];
                a0 = ffma2(wr_[2 * q],     hv.x, a0);
                a1 = ffma2(wr_[2 * q + 1], hv.y, a1);
                a2 = ffma2(wz_[2 * q],     hv.x, a2);
                a3 = ffma2(wz_[2 * q + 1], hv.y, a3);
            }
            float lo, hi, p;
            ull s;
            s = fadd2(a0, a1); unpack2(s, lo, hi); p = lo + hi;
            float hr = p + __shfl_xor_sync(0xFFFFFFFFu, p, 1);
            r = fsigmoid(ir + hr);                 // MUFU chain drains under pass 2
            s = fadd2(a2, a3); unpack2(s, lo, hi); p = lo + hi;
            float hz = p + __shfl_xor_sync(0xFFFFFFFFu, p, 1);
            z = fsigmoid(iz + hz);                 // ditto
        }

        // ---- pass 2: n gate chain (h re-read: broadcast LDS, LSU pipe idle) ----
        float hn;
        {
            ull b0 = 0ull, b1 = 0ull, b2 = 0ull, b3 = 0ull;
            #pragma unroll
            for (int q = 0; q < 16; q += 2) {
                ulonglong2 hv0 = hp[q];
                ulonglong2 hv1 = hp[q + 1];
                b0 = ffma2(wn_[2 * q],     hv0.x, b0);
                b1 = ffma2(wn_[2 * q + 1], hv0.y, b1);
                b2 = ffma2(wn_[2 * q + 2], hv1.x, b2);
                b3 = ffma2(wn_[2 * q + 3], hv1.y, b3);
            }
            ull s = fadd2(fadd2(b0, b2), fadd2(b1, b3));
            float lo, hi; unpack2(s, lo, hi);
            float p = lo + hi;
            hn = p + __shfl_xor_sync(0xFFFFFFFFu, p, 1);
        }

        // ---- tail: candidate + update ----
        // c computes in the shadow of the n-shfl (r is long since ready)
        float c    = fmaf(r, bni, inq);
        float n    = ftanh_f(fmaf(r, hn, c));
        float hnew = n + z * (h_old - n);               // equinox GRUCell
        h_old = hnew;

        if (half == 0) {
            h_sm[(t + 1) & 1][jidx] = hnew;             // double-buffered h
            if (j < LINW) g_hbuf[(size_t)t * LINW + j] = hnew;
        }
        ir = ir1; iz = iz1; inq = in1;
        ir1 = ir2; iz1 = iz2; in1 = in2;

        __syncthreads();   // single barrier per step
    }
}

// ============================================================================
// Kernel C: out[t] = dot(h[t][:32], x_lin[t]) + lin_bias
// ============================================================================
__global__ void out_kernel(
    const float* __restrict__ x_lin,
    const float* __restrict__ lin_bias,
    float* __restrict__ out)
{
    int t = blockIdx.x * blockDim.x + threadIdx.x;
    if (t >= T_STEPS) return;
    const float4* h4 = (const float4*)(g_hbuf + (size_t)t * LINW);
    const float4* x4 = (const float4*)(x_lin + (size_t)t * LINW);
    float acc = 0.0f;
    #pragma unroll
    for (int q = 0; q < 8; q++) {
        float4 a = h4[q], b = x4[q];
        acc += a.x * b.x + a.y * b.y + a.z * b.z + a.w * b.w;
    }
    out[t] = acc + lin_bias[0];
}

// ============================================================================
extern "C" void kernel_launch(void* const* d_in, const int* in_sizes, int n_in,
                              void* d_out, int out_size)
{
    const float* in_gru   = (const float*)d_in[0];  // (T, 96)
    const float* in_lin   = (const float*)d_in[1];  // (T, 32)
    const float* init_h   = (const float*)d_in[2];  // (128,)
    const float* w_ih     = (const float*)d_in[3];  // (384, 96)
    const float* w_hh     = (const float*)d_in[4];  // (384, 128)
    const float* b_ih     = (const float*)d_in[5];  // (384,)
    const float* b_n      = (const float*)d_in[6];  // (128,)
    const float* lin_bias = (const float*)d_in[7];  // (1,)

    igates_kernel<<<T_STEPS / 64, 384>>>(in_gru, w_ih, b_ih);
    scan_kernel<<<1, 256>>>(init_h, w_hh, b_n);
    out_kernel<<<T_STEPS / 256, 256>>>(in_lin, lin_bias, (float*)d_out);
}